// round 16
// baseline (speedup 1.0000x reference)
#include <cuda_runtime.h>
#include <math.h>
#include <stdint.h>

#define HIDDEN 1024
#define MEM 32
#define KEY 32
#define VAL 32
#define BATCH 2048
#define TLEN 64
#define BT (BATCH*TLEN)   /* 131072 */
#define NWARMUP 4

/* ---------------- proj tiling --------------------------------------------- */
#define BMp 128            /* rows per CTA */
#define BNp 96             /* proj cols (gate handled separately) */
#define BKp 16             /* base B-pack granularity */
#define NCHUNKS (HIDDEN/BKp)   /* 64 */
#define NCH32 (HIDDEN/32)      /* 32 */
/* shared smem layout (both proj variants): As[2][32][130]+Bs[2][32][96]+Gs[2][32] */
#define SMEM32 ((2*32*130 + 2*32*96 + 2*32) * 4)   /* 58368 B */

/* ---------------- scratch (static device arrays; no allocation) ----------- */
__device__ float g_Q [BT*KEY];
__device__ float g_FK[BT*KEY];
__device__ float g_FV[BT*VAL];
__device__ float g_P [BT];          /* sigmoid(gate logit), precomputed */
/* B weights, scalar, interleaved: [chunk16][kk][j*16+colgrp] */
__device__ float g_B[NCHUNKS][BKp][BNp];

/* ---------------- helpers -------------------------------------------------- */
__device__ __forceinline__ void ffma2(unsigned long long& d,
                                      unsigned long long a,
                                      unsigned long long b) {
    asm("fma.rn.f32x2 %0, %1, %2, %0;" : "+l"(d) : "l"(a), "l"(b));
}
__device__ __forceinline__ unsigned long long dup2(float b) {
    unsigned long long r;
    unsigned u = __float_as_uint(b);
    asm("mov.b64 %0, {%1, %1};" : "=l"(r) : "r"(u));
    return r;
}
__device__ __forceinline__ float f2lo(unsigned long long v) {
    return __uint_as_float((unsigned)(v & 0xffffffffu));
}
__device__ __forceinline__ float f2hi(unsigned long long v) {
    return __uint_as_float((unsigned)(v >> 32));
}
__device__ __forceinline__ unsigned redux_umax(unsigned v) {
    unsigned r;
    asm("redux.sync.max.u32 %0, %1, 0xffffffff;" : "=r"(r) : "r"(v));
    return r;
}
__device__ __forceinline__ unsigned redux_umin(unsigned v) {
    unsigned r;
    asm("redux.sync.min.u32 %0, %1, 0xffffffff;" : "=r"(r) : "r"(v));
    return r;
}
__device__ __forceinline__ void cp_async16(float* smem_dst, const float* gmem_src) {
    unsigned sa = (unsigned)__cvta_generic_to_shared(smem_dst);
    asm volatile("cp.async.cg.shared.global [%0], [%1], 16;"
                 :: "r"(sa), "l"(gmem_src));
}
__device__ __forceinline__ void cp_async_commit() {
    asm volatile("cp.async.commit_group;");
}
__device__ __forceinline__ void cp_async_wait0() {
    asm volatile("cp.async.wait_group 0;" ::: "memory");
}

/* ---------------- prep: interleave weights --------------------------------- */
__global__ __launch_bounds__(256) void prep_kernel(
    const float* __restrict__ Wq, const float* __restrict__ Wk,
    const float* __restrict__ Wv)
{
    int idx = blockIdx.x * 256 + threadIdx.x;    /* 64*16*96 = 98304 */
    int c   = idx / (BKp * BNp);
    int rem = idx % (BKp * BNp);
    int kk  = rem / BNp;
    int col = rem % BNp;
    int k   = c * BKp + kk;

    float b;
    if      (col < 32) b = Wq[col * HIDDEN + k];
    else if (col < 64) b = Wk[(col - 32) * HIDDEN + k];
    else               b = Wv[(col - 64) * HIDDEN + k];

    int colgrp = col / 6;
    int j      = col % 6;
    g_B[c][kk][j * 16 + colgrp] = b;
}

/* ---------------- proj32: R13 winner (fallback) ---------------------------- */
__global__ __launch_bounds__(256) void proj_kernel32(
    const float* __restrict__ hmat,
    const float* __restrict__ Wg, const float* __restrict__ bg,
    const float* __restrict__ bq, const float* __restrict__ bk_,
    const float* __restrict__ bv)
{
    extern __shared__ float dsm[];
    float* AsP = dsm;                       /* [2][32][130] */
    float* BsP = dsm + 2 * 32 * 130;        /* [2][32][96]  */
    float* GsP = BsP + 2 * 32 * 96;         /* [2][32]      */
#define AS32(s,kk) (AsP + ((s) * 32 + (kk)) * 130)
#define BS32(s,kk) (BsP + ((s) * 32 + (kk)) * 96)
#define GS32(s,kk) (GsP + (s) * 32 + (kk))

    const int tid    = threadIdx.x;
    const int colgrp = tid & 15;
    const int rowgrp = tid >> 4;
    const long r0    = (long)blockIdx.x * BMp;

    unsigned long long acc[4][6];
    #pragma unroll
    for (int i = 0; i < 4; i++)
        #pragma unroll
        for (int j = 0; j < 6; j++) acc[i][j] = 0ull;
    float accg = 0.f;

    float4 av[4];
    float2 bvv[6];
    float  gv;
    {
        #pragma unroll
        for (int q = 0; q < 4; q++) {
            int i   = tid + 256 * q;
            int row = i >> 3;
            int kg  = (i & 7) * 4;
            av[q] = *(const float4*)(hmat + (r0 + row) * HIDDEN + kg);
        }
        const float2* bsrc = (const float2*)&g_B[0][0][0];
        #pragma unroll
        for (int q = 0; q < 6; q++) bvv[q] = bsrc[tid + 256 * q];
        gv = (tid < 32) ? Wg[tid] : 0.f;
    }
    {
        #pragma unroll
        for (int q = 0; q < 4; q++) {
            int i   = tid + 256 * q;
            int row = i >> 3;
            int kg  = (i & 7) * 4;
            AS32(0, kg+0)[row] = av[q].x;
            AS32(0, kg+1)[row] = av[q].y;
            AS32(0, kg+2)[row] = av[q].z;
            AS32(0, kg+3)[row] = av[q].w;
        }
        float2* bdst = (float2*)BS32(0, 0);
        #pragma unroll
        for (int q = 0; q < 6; q++) bdst[tid + 256 * q] = bvv[q];
        if (tid < 32) *GS32(0, tid) = gv;
    }
    __syncthreads();

    for (int c = 0; c < NCH32; c++) {
        const int s = c & 1;
        if (c + 1 < NCH32) {
            const int k0n = (c + 1) * 32;
            #pragma unroll
            for (int q = 0; q < 4; q++) {
                int i   = tid + 256 * q;
                int row = i >> 3;
                int kg  = (i & 7) * 4;
                av[q] = *(const float4*)(hmat + (r0 + row) * HIDDEN + k0n + kg);
            }
            const float2* bsrc = (const float2*)&g_B[2 * (c + 1)][0][0];
            #pragma unroll
            for (int q = 0; q < 6; q++) bvv[q] = bsrc[tid + 256 * q];
            gv = (tid < 32) ? Wg[k0n + tid] : 0.f;
        }

        #pragma unroll
        for (int kk = 0; kk < 32; kk++) {
            unsigned long long a[4], b[6];
            const float* Ap = AS32(s, kk);
            #pragma unroll
            for (int i = 0; i < 4; i++)
                a[i] = *(const unsigned long long*)(Ap + rowgrp * 8 + 2 * i);
            const float* Bp = BS32(s, kk);
            #pragma unroll
            for (int j = 0; j < 6; j++)
                b[j] = dup2(Bp[j * 16 + colgrp]);
            #pragma unroll
            for (int i = 0; i < 4; i++)
                #pragma unroll
                for (int j = 0; j < 6; j++)
                    ffma2(acc[i][j], a[i], b[j]);
            if (tid < 128) accg = fmaf(Ap[tid], *GS32(s, kk), accg);
        }

        if (c + 1 < NCH32) {
            const int sn = s ^ 1;
            #pragma unroll
            for (int q = 0; q < 4; q++) {
                int i   = tid + 256 * q;
                int row = i >> 3;
                int kg  = (i & 7) * 4;
                AS32(sn, kg+0)[row] = av[q].x;
                AS32(sn, kg+1)[row] = av[q].y;
                AS32(sn, kg+2)[row] = av[q].z;
                AS32(sn, kg+3)[row] = av[q].w;
            }
            float2* bdst = (float2*)BS32(sn, 0);
            #pragma unroll
            for (int q = 0; q < 6; q++) bdst[tid + 256 * q] = bvv[q];
            if (tid < 32) *GS32(sn, tid) = gv;
        }
        __syncthreads();
    }

    /* epilogue (8 rows x 6 cols per thread) */
    const int C = colgrp * 6;
    float bias[6];
    #pragma unroll
    for (int j = 0; j < 6; j++) {
        int col = C + j;
        bias[j] = (col < 32) ? bq[col] : (col < 64) ? bk_[col - 32] : bv[col - 64];
    }
    #pragma unroll
    for (int i = 0; i < 4; i++) {
        long row0 = r0 + rowgrp * 8 + 2 * i;
        float v0[6], v1[6];
        #pragma unroll
        for (int j = 0; j < 6; j++) {
            v0[j] = f2lo(acc[i][j]) + bias[j];
            v1[j] = f2hi(acc[i][j]) + bias[j];
        }
        #pragma unroll
        for (int jj = 0; jj < 6; jj += 2) {
            int col = C + jj;
            float* dst; int cc;
            if      (col < 32) { dst = g_Q;  cc = col; }
            else if (col < 64) { dst = g_FK; cc = col - 32; }
            else               { dst = g_FV; cc = col - 64; }
            *(float2*)(dst + row0 * 32 + cc)       = make_float2(v0[jj], v0[jj+1]);
            *(float2*)(dst + (row0 + 1) * 32 + cc) = make_float2(v1[jj], v1[jj+1]);
        }
    }
    if (tid < 128) {
        float gx = accg + bg[0];
        g_P[r0 + tid] = 1.f / (1.f + expf(-gx));
    }
}

/* ---------------- proj512: 512 threads, 4x6 microtile, 2x warps/SM --------- */
__global__ __launch_bounds__(512) void proj_kernel512(
    const float* __restrict__ hmat,
    const float* __restrict__ Wg, const float* __restrict__ bg,
    const float* __restrict__ bq, const float* __restrict__ bk_,
    const float* __restrict__ bv)
{
    extern __shared__ float dsm[];
    float* AsP = dsm;                       /* [2][32][130] */
    float* BsP = dsm + 2 * 32 * 130;        /* [2][32][96]  */
    float* GsP = BsP + 2 * 32 * 96;         /* [2][32]      */
#define AS5(s,kk) (AsP + ((s) * 32 + (kk)) * 130)
#define BS5(s)    (BsP + (s) * 32 * 96)
#define GS5(s)    (GsP + (s) * 32)

    const int tid    = threadIdx.x;
    const int colgrp = tid & 15;
    const int rowgrp = tid >> 4;            /* 0..31, 4 rows each */
    const long r0    = (long)blockIdx.x * BMp;

    unsigned long long acc[2][6];           /* 4 rows = 2 row-pairs x 6 cols */
    #pragma unroll
    for (int i = 0; i < 2; i++)
        #pragma unroll
        for (int j = 0; j < 6; j++) acc[i][j] = 0ull;
    float accg = 0.f;

    float4 av[2];        /* A: 4096 floats / 512 thr = 2 float4 (8 regs) */
    float  gv;

    /* prologue: chunk 0 (B via cp.async: 32*96 floats = 768 float4) */
    {
        #pragma unroll
        for (int q = 0; q < 2; q++) {
            int i   = tid + 512 * q;      /* 0..1023 */
            int row = i >> 3;
            int kg  = (i & 7) * 4;
            av[q] = *(const float4*)(hmat + (r0 + row) * HIDDEN + kg);
        }
        gv = (tid < 32) ? Wg[tid] : 0.f;
        const float* bsrc = &g_B[0][0][0];
        #pragma unroll
        for (int q = 0; q < 2; q++) {
            int i = tid + 512 * q;
            if (i < 768)
                cp_async16(BS5(0) + i * 4, bsrc + i * 4);
        }
        cp_async_commit();

        #pragma unroll
        for (int q = 0; q < 2; q++) {
            int i   = tid + 512 * q;
            int row = i >> 3;
            int kg  = (i & 7) * 4;
            AS5(0, kg+0)[row] = av[q].x;
            AS5(0, kg+1)[row] = av[q].y;
            AS5(0, kg+2)[row] = av[q].z;
            AS5(0, kg+3)[row] = av[q].w;
        }
        if (tid < 32) GS5(0)[tid] = gv;
        cp_async_wait0();
    }
    __syncthreads();

    for (int c = 0; c < NCH32; c++) {
        const int s = c & 1;
        const int sn = s ^ 1;

        if (c + 1 < NCH32) {
            const int k0n = (c + 1) * 32;
            #pragma unroll
            for (int q = 0; q < 2; q++) {
                int i   = tid + 512 * q;
                int row = i >> 3;
                int kg  = (i & 7) * 4;
                av[q] = *(const float4*)(hmat + (r0 + row) * HIDDEN + k0n + kg);
            }
            gv = (tid < 32) ? Wg[k0n + tid] : 0.f;
            const float* bsrc = &g_B[2 * (c + 1)][0][0];
            #pragma unroll
            for (int q = 0; q < 2; q++) {
                int i = tid + 512 * q;
                if (i < 768)
                    cp_async16(BS5(sn) + i * 4, bsrc + i * 4);
            }
            cp_async_commit();
        }

        /* compute 32 kk from stage s */
        #pragma unroll
        for (int kk = 0; kk < 32; kk++) {
            const float* Ap = AS5(s, kk);
            const float* Bp = BS5(s) + kk * 96;
            unsigned long long a[2], b[6];
            #pragma unroll
            for (int i = 0; i < 2; i++)
                a[i] = *(const unsigned long long*)(Ap + rowgrp * 4 + 2 * i);
            #pragma unroll
            for (int j = 0; j < 6; j++)
                b[j] = dup2(Bp[j * 16 + colgrp]);
            #pragma unroll
            for (int i = 0; i < 2; i++)
                #pragma unroll
                for (int j = 0; j < 6; j++)
                    ffma2(acc[i][j], a[i], b[j]);
            if (tid < 128) accg = fmaf(Ap[tid], GS5(s)[kk], accg);
        }

        if (c + 1 < NCH32) {
            #pragma unroll
            for (int q = 0; q < 2; q++) {
                int i   = tid + 512 * q;
                int row = i >> 3;
                int kg  = (i & 7) * 4;
                AS5(sn, kg+0)[row] = av[q].x;
                AS5(sn, kg+1)[row] = av[q].y;
                AS5(sn, kg+2)[row] = av[q].z;
                AS5(sn, kg+3)[row] = av[q].w;
            }
            if (tid < 32) GS5(sn)[tid] = gv;
            cp_async_wait0();
        }
        __syncthreads();
    }

    /* epilogue: 4 rows x 6 cols per thread */
    const int C = colgrp * 6;
    float bias[6];
    #pragma unroll
    for (int j = 0; j < 6; j++) {
        int col = C + j;
        bias[j] = (col < 32) ? bq[col] : (col < 64) ? bk_[col - 32] : bv[col - 64];
    }
    #pragma unroll
    for (int i = 0; i < 2; i++) {
        long row0 = r0 + rowgrp * 4 + 2 * i;
        float v0[6], v1[6];
        #pragma unroll
        for (int j = 0; j < 6; j++) {
            v0[j] = f2lo(acc[i][j]) + bias[j];
            v1[j] = f2hi(acc[i][j]) + bias[j];
        }
        #pragma unroll
        for (int jj = 0; jj < 6; jj += 2) {
            int col = C + jj;
            float* dst; int cc;
            if      (col < 32) { dst = g_Q;  cc = col; }
            else if (col < 64) { dst = g_FK; cc = col - 32; }
            else               { dst = g_FV; cc = col - 64; }
            *(float2*)(dst + row0 * 32 + cc)       = make_float2(v0[jj], v0[jj+1]);
            *(float2*)(dst + (row0 + 1) * 32 + cc) = make_float2(v1[jj], v1[jj+1]);
        }
    }
    if (tid < 128) {
        float gx = accg + bg[0];
        g_P[r0 + tid] = 1.f / (1.f + expf(-gx));
    }
}

/* ---------------- Kernel 2: recurrence (R12 verbatim) ---------------------- */
#define NW 2

__global__ __launch_bounds__(32*NW) void rnn_kernel(float* __restrict__ es,
                                                    float* __restrict__ ps)
{
    __shared__ float Vs [NW][MEM][VAL+1];
    __shared__ float qs [NW][KEY];
    __shared__ float fks[NW][KEY];
    __shared__ float fvs[NW][VAL];
    __shared__ float ats[NW][MEM];

    const int w    = threadIdx.x >> 5;
    const int lane = threadIdx.x & 31;
    const int b    = blockIdx.x * NW + w;
    const unsigned FULL = 0xffffffffu;
    const float scale = 0.17677669529663688f;

    float K[KEY];
    #pragma unroll
    for (int j = 0; j < KEY; j++) { K[j] = 0.f; Vs[w][lane][j] = 0.f; }
    float Tf = 0.f, msk = 0.f;
    __syncwarp();

    const long row0 = (long)b * TLEN;
    float qv  = g_Q [row0*KEY + lane];
    float fkv = g_FK[row0*KEY + lane];
    float fvv = g_FV[row0*VAL + lane];
    float pv  = g_P [row0];

    for (int t = 0; t < TLEN; t++) {
        const long row  = row0 + t;
        const long nrow = (t < TLEN-1) ? row + 1 : row;

        float nq  = g_Q [nrow*KEY + lane];
        float nfk = g_FK[nrow*KEY + lane];
        float nfv = g_FV[nrow*VAL + lane];
        float npv = g_P [nrow];

        qs [w][lane] = qv;
        fks[w][lane] = fkv;
        fvs[w][lane] = fvv;
        __syncwarp();

        float lg = 0.f;
        #pragma unroll
        for (int j = 0; j < KEY; j++) lg = fmaf(K[j], qs[w][j], lg);
        lg *= scale;
        float lm = fmaf(1.0f - msk, -1e9f, lg);

        unsigned ub  = __float_as_uint(lm);
        unsigned key = ub ^ ((unsigned)((int)ub >> 31) | 0x80000000u);
        unsigned km  = redux_umax(key);
        unsigned mb  = (km & 0x80000000u) ? (km ^ 0x80000000u) : ~km;
        float mx = __uint_as_float(mb);

        float ex = expf(lm - mx);
        float sm = ex;
        #pragma unroll
        for (int off = 16; off; off >>= 1)
            sm += __shfl_xor_sync(FULL, sm, off);
        float attn = ex / sm;
        ats[w][lane] = attn;

        unsigned ab = __float_as_uint(attn);
        unsigned am = redux_umax(ab);
        int amax = __ffs(__ballot_sync(FULL, ab == am)) - 1;
        __syncwarp();

        float r0a = 0.f, r1a = 0.f;
        #pragma unroll
        for (int m = 0; m < 16; m++)
            r0a = fmaf(ats[w][m], Vs[w][m][lane], r0a);
        #pragma unroll
        for (int m = 16; m < 32; m++)
            r1a = fmaf(ats[w][m], Vs[w][m][lane], r1a);
        float r = r0a + r1a;

        unsigned bal = __ballot_sync(FULL, msk != 0.f);
        bool empty = (bal == 0u);
        bool warm  = (t < NWARMUP);
        float p = pv;
        float gate = (empty || warm) ? 0.f : p;
        bool wr = empty || warm || (p < 0.5f);

        float om = 1.0f - gate;
        float e  = gate * r + om * fvv;
        es[row*VAL + lane] = e;
        if (lane == 0) ps[row] = p;

        float evv = Tf + msk * 0.001f;
        unsigned eb = __float_as_uint(evv);
        unsigned em = redux_umin(eb);
        int evict = __ffs(__ballot_sync(FULL, eb == em)) - 1;

        if (wr && lane == evict) {
            msk = 1.f;
            #pragma unroll
            for (int j = 0; j < KEY; j++) {
                K[j] = fks[w][j];
                Vs[w][lane][j] = fvs[w][j];
            }
        }
        int bslot = wr ? evict : amax;
        float A = Tf * 0.85f;
        Tf = (lane == bslot) ? (A + (1.0f - A)) : A;
        __syncwarp();

        qv = nq; fkv = nfk; fvv = nfv; pv = npv;
    }
}

/* ---------------- launch ---------------------------------------------------- */
extern "C" void kernel_launch(void* const* d_in, const int* in_sizes, int n_in,
                              void* d_out, int out_size)
{
    const float* h  = (const float*)d_in[0];
    const float* Wg = (const float*)d_in[1];
    const float* bg = (const float*)d_in[2];
    const float* Wq = (const float*)d_in[3];
    const float* bq = (const float*)d_in[4];
    const float* Wk = (const float*)d_in[5];
    const float* bk = (const float*)d_in[6];
    const float* Wv = (const float*)d_in[7];
    const float* bv = (const float*)d_in[8];

    float* es = (float*)d_out;
    float* ps = es + ((long)out_size - BT);

    prep_kernel<<<(NCHUNKS*BKp*BNp)/256, 256>>>(Wq, Wk, Wv);

    /* dispatch: proj512 only if it truly doubles warps/SM without spills */
    cudaFuncSetAttribute(proj_kernel512,
                         cudaFuncAttributeMaxDynamicSharedMemorySize, SMEM32);
    int nb512 = 0;
    cudaOccupancyMaxActiveBlocksPerMultiprocessor(&nb512, proj_kernel512, 512, SMEM32);
    cudaFuncAttributes a512;
    cudaFuncGetAttributes(&a512, proj_kernel512);
    if (nb512 >= 2 && a512.localSizeBytes == 0) {
        proj_kernel512<<<BT/BMp, 512, SMEM32>>>(h, Wg, bg, bq, bk, bv);
    } else {
        cudaFuncSetAttribute(proj_kernel32,
                             cudaFuncAttributeMaxDynamicSharedMemorySize, SMEM32);
        proj_kernel32<<<BT/BMp, 256, SMEM32>>>(h, Wg, bg, bq, bk, bv);
    }

    rnn_kernel<<<BATCH/NW, 32*NW>>>(es, ps);
}

// round 17
// speedup vs baseline: 1.2053x; 1.2053x over previous
#include <cuda_runtime.h>
#include <math.h>
#include <stdint.h>

#define HIDDEN 1024
#define MEM 32
#define KEY 32
#define VAL 32
#define BATCH 2048
#define TLEN 64
#define BT (BATCH*TLEN)   /* 131072 */
#define NWARMUP 4

/* ---------------- proj tiling --------------------------------------------- */
#define BMp 128            /* rows per CTA */
#define BNp 96             /* proj cols (gate handled separately) */
#define BKp 16             /* base B-pack granularity */
#define NCHUNKS (HIDDEN/BKp)   /* 64 */
#define NCH32 (HIDDEN/32)      /* 32 */
/* proj32 dynamic smem: As[2][32][130] + Bs[2][32][96] + Gs[2][32] */
#define SMEM32 ((2*32*130 + 2*32*96 + 2*32) * 4)   /* 58368 B */

/* ---------------- scratch (static device arrays; no allocation) ----------- */
__device__ float g_Q [BT*KEY];
__device__ float g_FK[BT*KEY];
__device__ float g_FV[BT*VAL];
__device__ float g_P [BT];          /* sigmoid(gate logit), precomputed */
/* B weights, scalar, interleaved: [chunk16][kk][j*16+colgrp] */
__device__ float g_B[NCHUNKS][BKp][BNp];

/* ---------------- helpers -------------------------------------------------- */
__device__ __forceinline__ void ffma2(unsigned long long& d,
                                      unsigned long long a,
                                      unsigned long long b) {
    asm("fma.rn.f32x2 %0, %1, %2, %0;" : "+l"(d) : "l"(a), "l"(b));
}
__device__ __forceinline__ unsigned long long dup2(float b) {
    unsigned long long r;
    unsigned u = __float_as_uint(b);
    asm("mov.b64 %0, {%1, %1};" : "=l"(r) : "r"(u));
    return r;
}
__device__ __forceinline__ float f2lo(unsigned long long v) {
    return __uint_as_float((unsigned)(v & 0xffffffffu));
}
__device__ __forceinline__ float f2hi(unsigned long long v) {
    return __uint_as_float((unsigned)(v >> 32));
}
__device__ __forceinline__ unsigned redux_umax(unsigned v) {
    unsigned r;
    asm("redux.sync.max.u32 %0, %1, 0xffffffff;" : "=r"(r) : "r"(v));
    return r;
}
__device__ __forceinline__ unsigned redux_umin(unsigned v) {
    unsigned r;
    asm("redux.sync.min.u32 %0, %1, 0xffffffff;" : "=r"(r) : "r"(v));
    return r;
}

/* ---------------- prep: interleave weights --------------------------------- */
__global__ __launch_bounds__(256) void prep_kernel(
    const float* __restrict__ Wq, const float* __restrict__ Wk,
    const float* __restrict__ Wv)
{
    int idx = blockIdx.x * 256 + threadIdx.x;    /* 64*16*96 = 98304 */
    int c   = idx / (BKp * BNp);
    int rem = idx % (BKp * BNp);
    int kk  = rem / BNp;
    int col = rem % BNp;
    int k   = c * BKp + kk;

    float b;
    if      (col < 32) b = Wq[col * HIDDEN + k];
    else if (col < 64) b = Wk[(col - 32) * HIDDEN + k];
    else               b = Wv[(col - 64) * HIDDEN + k];

    int colgrp = col / 6;
    int j      = col % 6;
    g_B[c][kk][j * 16 + colgrp] = b;
}

/* ---------------- proj32: R13 winner, byte-identical ----------------------- */
__global__ __launch_bounds__(256) void proj_kernel32(
    const float* __restrict__ hmat,
    const float* __restrict__ Wg, const float* __restrict__ bg,
    const float* __restrict__ bq, const float* __restrict__ bk_,
    const float* __restrict__ bv)
{
    extern __shared__ float dsm[];
    float* AsP = dsm;                       /* [2][32][130] */
    float* BsP = dsm + 2 * 32 * 130;        /* [2][32][96]  */
    float* GsP = BsP + 2 * 32 * 96;         /* [2][32]      */
#define AS32(s,kk) (AsP + ((s) * 32 + (kk)) * 130)
#define BS32(s,kk) (BsP + ((s) * 32 + (kk)) * 96)
#define GS32(s,kk) (GsP + (s) * 32 + (kk))

    const int tid    = threadIdx.x;
    const int colgrp = tid & 15;
    const int rowgrp = tid >> 4;
    const long r0    = (long)blockIdx.x * BMp;

    unsigned long long acc[4][6];
    #pragma unroll
    for (int i = 0; i < 4; i++)
        #pragma unroll
        for (int j = 0; j < 6; j++) acc[i][j] = 0ull;
    float accg = 0.f;

    float4 av[4];
    float2 bvv[6];
    float  gv;
    {
        #pragma unroll
        for (int q = 0; q < 4; q++) {
            int i   = tid + 256 * q;
            int row = i >> 3;
            int kg  = (i & 7) * 4;
            av[q] = *(const float4*)(hmat + (r0 + row) * HIDDEN + kg);
        }
        const float2* bsrc = (const float2*)&g_B[0][0][0];
        #pragma unroll
        for (int q = 0; q < 6; q++) bvv[q] = bsrc[tid + 256 * q];
        gv = (tid < 32) ? Wg[tid] : 0.f;
    }
    {
        #pragma unroll
        for (int q = 0; q < 4; q++) {
            int i   = tid + 256 * q;
            int row = i >> 3;
            int kg  = (i & 7) * 4;
            AS32(0, kg+0)[row] = av[q].x;
            AS32(0, kg+1)[row] = av[q].y;
            AS32(0, kg+2)[row] = av[q].z;
            AS32(0, kg+3)[row] = av[q].w;
        }
        float2* bdst = (float2*)BS32(0, 0);
        #pragma unroll
        for (int q = 0; q < 6; q++) bdst[tid + 256 * q] = bvv[q];
        if (tid < 32) *GS32(0, tid) = gv;
    }
    __syncthreads();

    for (int c = 0; c < NCH32; c++) {
        const int s = c & 1;
        if (c + 1 < NCH32) {
            const int k0n = (c + 1) * 32;
            #pragma unroll
            for (int q = 0; q < 4; q++) {
                int i   = tid + 256 * q;
                int row = i >> 3;
                int kg  = (i & 7) * 4;
                av[q] = *(const float4*)(hmat + (r0 + row) * HIDDEN + k0n + kg);
            }
            const float2* bsrc = (const float2*)&g_B[2 * (c + 1)][0][0];
            #pragma unroll
            for (int q = 0; q < 6; q++) bvv[q] = bsrc[tid + 256 * q];
            gv = (tid < 32) ? Wg[k0n + tid] : 0.f;
        }

        #pragma unroll
        for (int kk = 0; kk < 32; kk++) {
            unsigned long long a[4], b[6];
            const float* Ap = AS32(s, kk);
            #pragma unroll
            for (int i = 0; i < 4; i++)
                a[i] = *(const unsigned long long*)(Ap + rowgrp * 8 + 2 * i);
            const float* Bp = BS32(s, kk);
            #pragma unroll
            for (int j = 0; j < 6; j++)
                b[j] = dup2(Bp[j * 16 + colgrp]);
            #pragma unroll
            for (int i = 0; i < 4; i++)
                #pragma unroll
                for (int j = 0; j < 6; j++)
                    ffma2(acc[i][j], a[i], b[j]);
            if (tid < 128) accg = fmaf(Ap[tid], *GS32(s, kk), accg);
        }

        if (c + 1 < NCH32) {
            const int sn = s ^ 1;
            #pragma unroll
            for (int q = 0; q < 4; q++) {
                int i   = tid + 256 * q;
                int row = i >> 3;
                int kg  = (i & 7) * 4;
                AS32(sn, kg+0)[row] = av[q].x;
                AS32(sn, kg+1)[row] = av[q].y;
                AS32(sn, kg+2)[row] = av[q].z;
                AS32(sn, kg+3)[row] = av[q].w;
            }
            float2* bdst = (float2*)BS32(sn, 0);
            #pragma unroll
            for (int q = 0; q < 6; q++) bdst[tid + 256 * q] = bvv[q];
            if (tid < 32) *GS32(sn, tid) = gv;
        }
        __syncthreads();
    }

    /* epilogue */
    const int C = colgrp * 6;
    float bias[6];
    #pragma unroll
    for (int j = 0; j < 6; j++) {
        int col = C + j;
        bias[j] = (col < 32) ? bq[col] : (col < 64) ? bk_[col - 32] : bv[col - 64];
    }
    #pragma unroll
    for (int i = 0; i < 4; i++) {
        long row0 = r0 + rowgrp * 8 + 2 * i;
        float v0[6], v1[6];
        #pragma unroll
        for (int j = 0; j < 6; j++) {
            v0[j] = f2lo(acc[i][j]) + bias[j];
            v1[j] = f2hi(acc[i][j]) + bias[j];
        }
        #pragma unroll
        for (int jj = 0; jj < 6; jj += 2) {
            int col = C + jj;
            float* dst; int cc;
            if      (col < 32) { dst = g_Q;  cc = col; }
            else if (col < 64) { dst = g_FK; cc = col - 32; }
            else               { dst = g_FV; cc = col - 64; }
            *(float2*)(dst + row0 * 32 + cc)       = make_float2(v0[jj], v0[jj+1]);
            *(float2*)(dst + (row0 + 1) * 32 + cc) = make_float2(v1[jj], v1[jj+1]);
        }
    }
    if (tid < 128) {
        float gx = accg + bg[0];
        g_P[r0 + tid] = 1.f / (1.f + expf(-gx));
    }
}

/* ---------------- Kernel 2: recurrence; evict/empty hoisted ---------------- */
#define NW 2

__global__ __launch_bounds__(32*NW) void rnn_kernel(float* __restrict__ es,
                                                    float* __restrict__ ps)
{
    __shared__ float Vs [NW][MEM][VAL+1];
    __shared__ float qs [NW][KEY];
    __shared__ float fks[NW][KEY];
    __shared__ float fvs[NW][VAL];
    __shared__ float ats[NW][MEM];

    const int w    = threadIdx.x >> 5;
    const int lane = threadIdx.x & 31;
    const int b    = blockIdx.x * NW + w;
    const unsigned FULL = 0xffffffffu;
    const float scale = 0.17677669529663688f;

    float K[KEY];
    #pragma unroll
    for (int j = 0; j < KEY; j++) { K[j] = 0.f; Vs[w][lane][j] = 0.f; }
    float Tf = 0.f, msk = 0.f;
    __syncwarp();

    const long row0 = (long)b * TLEN;
    float qv  = g_Q [row0*KEY + lane];
    float fkv = g_FK[row0*KEY + lane];
    float fvv = g_FV[row0*VAL + lane];
    float pv  = g_P [row0];

    for (int t = 0; t < TLEN; t++) {
        const long row  = row0 + t;
        const long nrow = (t < TLEN-1) ? row + 1 : row;

        float nq  = g_Q [nrow*KEY + lane];
        float nfk = g_FK[nrow*KEY + lane];
        float nfv = g_FV[nrow*VAL + lane];
        float npv = g_P [nrow];

        /* ---- HOISTED: depends only on previous-step state (Tf, msk) ----
           evict = argmin(Tf + msk*0.001), empty = no slot occupied.
           Issued first so redux/ballot latency overlaps the softmax chain. */
        float evv = Tf + msk * 0.001f;
        unsigned eb = __float_as_uint(evv);
        unsigned em = redux_umin(eb);
        int evict = __ffs(__ballot_sync(FULL, eb == em)) - 1;
        unsigned bal = __ballot_sync(FULL, msk != 0.f);
        bool empty = (bal == 0u);

        qs [w][lane] = qv;
        fks[w][lane] = fkv;
        fvs[w][lane] = fvv;
        __syncwarp();

        /* logits chain: order-preserving (decision-critical) */
        float lg = 0.f;
        #pragma unroll
        for (int j = 0; j < KEY; j++) lg = fmaf(K[j], qs[w][j], lg);
        lg *= scale;
        float lm = fmaf(1.0f - msk, -1e9f, lg);

        unsigned ub  = __float_as_uint(lm);
        unsigned key = ub ^ ((unsigned)((int)ub >> 31) | 0x80000000u);
        unsigned km  = redux_umax(key);
        unsigned mb  = (km & 0x80000000u) ? (km ^ 0x80000000u) : ~km;
        float mx = __uint_as_float(mb);

        float ex = expf(lm - mx);
        float sm = ex;
        #pragma unroll
        for (int off = 16; off; off >>= 1)
            sm += __shfl_xor_sync(FULL, sm, off);
        float attn = ex / sm;
        ats[w][lane] = attn;

        unsigned ab = __float_as_uint(attn);
        unsigned am = redux_umax(ab);
        int amax = __ffs(__ballot_sync(FULL, ab == am)) - 1;
        __syncwarp();

        /* retrv: 2-way split (feeds only e_t — continuous, no decisions) */
        float r0a = 0.f, r1a = 0.f;
        #pragma unroll
        for (int m = 0; m < 16; m++)
            r0a = fmaf(ats[w][m], Vs[w][m][lane], r0a);
        #pragma unroll
        for (int m = 16; m < 32; m++)
            r1a = fmaf(ats[w][m], Vs[w][m][lane], r1a);
        float r = r0a + r1a;

        bool warm  = (t < NWARMUP);
        float p = pv;
        float gate = (empty || warm) ? 0.f : p;
        bool wr = empty || warm || (p < 0.5f);

        float om = 1.0f - gate;
        float e  = gate * r + om * fvv;
        es[row*VAL + lane] = e;
        if (lane == 0) ps[row] = p;

        if (wr && lane == evict) {
            msk = 1.f;
            #pragma unroll
            for (int j = 0; j < KEY; j++) {
                K[j] = fks[w][j];
                Vs[w][lane][j] = fvs[w][j];
            }
        }
        int bslot = wr ? evict : amax;
        float A = Tf * 0.85f;
        Tf = (lane == bslot) ? (A + (1.0f - A)) : A;
        __syncwarp();

        qv = nq; fkv = nfk; fvv = nfv; pv = npv;
    }
}

/* ---------------- launch ---------------------------------------------------- */
extern "C" void kernel_launch(void* const* d_in, const int* in_sizes, int n_in,
                              void* d_out, int out_size)
{
    const float* h  = (const float*)d_in[0];
    const float* Wg = (const float*)d_in[1];
    const float* bg = (const float*)d_in[2];
    const float* Wq = (const float*)d_in[3];
    const float* bq = (const float*)d_in[4];
    const float* Wk = (const float*)d_in[5];
    const float* bk = (const float*)d_in[6];
    const float* Wv = (const float*)d_in[7];
    const float* bv = (const float*)d_in[8];

    float* es = (float*)d_out;
    float* ps = es + ((long)out_size - BT);

    prep_kernel<<<(NCHUNKS*BKp*BNp)/256, 256>>>(Wq, Wk, Wv);

    cudaFuncSetAttribute(proj_kernel32,
                         cudaFuncAttributeMaxDynamicSharedMemorySize, SMEM32);
    proj_kernel32<<<BT/BMp, 256, SMEM32>>>(h, Wg, bg, bq, bk, bv);

    rnn_kernel<<<BATCH/NW, 32*NW>>>(es, ps);
}